// round 2
// baseline (speedup 1.0000x reference)
#include <cuda_runtime.h>
#include <math.h>

#define BATCH 4
#define CH 256
#define NSP 4096            // h*w = 64*64
#define GROUPS 8
#define CPG 32              // channels per group
#define GELEMS (CPG*NSP)    // 131072 elements per (b, group)
#define EPS 1e-5f

// ---------------- scratch (device globals; no allocation allowed) ----------------
__device__ float g_xn[BATCH*CH*NSP];        // groupnorm output            16.8 MB
__device__ float g_qkv[BATCH*3*CH*NSP];     // qkv conv output [b][o][p]   50.3 MB
__device__ float g_vT[BATCH*NSP*CH];        // V transposed   [b][p][c]    16.8 MB
__device__ float g_attn[BATCH*NSP*CH];      // attn output    [b][p][c]    16.8 MB
__device__ float g_gnpart[BATCH*GROUPS*8*2];

// ---------------- GroupNorm: partial reduction ----------------
__global__ void gn_partial(const float* __restrict__ x) {
    int blk = blockIdx.x;          // 32 (b,g) * 8 slices
    int bg = blk >> 3, slice = blk & 7;
    const float4* p4 = (const float4*)(x + bg*GELEMS + slice*(GELEMS/8));
    float s = 0.f, sq = 0.f;
    for (int i = threadIdx.x; i < GELEMS/8/4; i += 256) {
        float4 v = p4[i];
        s  += v.x + v.y + v.z + v.w;
        sq += v.x*v.x + v.y*v.y + v.z*v.z + v.w*v.w;
    }
    __shared__ float ss[256], ssq[256];
    ss[threadIdx.x] = s; ssq[threadIdx.x] = sq;
    __syncthreads();
    for (int st = 128; st > 0; st >>= 1) {
        if (threadIdx.x < st) {
            ss[threadIdx.x]  += ss[threadIdx.x + st];
            ssq[threadIdx.x] += ssq[threadIdx.x + st];
        }
        __syncthreads();
    }
    if (threadIdx.x == 0) {
        g_gnpart[blk*2 + 0] = ss[0];
        g_gnpart[blk*2 + 1] = ssq[0];
    }
}

// ---------------- GroupNorm: apply ----------------
__global__ void gn_apply(const float* __restrict__ x,
                         const float* __restrict__ gamma,
                         const float* __restrict__ beta) {
    int gi = blockIdx.x * 256 + threadIdx.x;     // float4 index
    int bg = gi >> 15;                            // (b,g) index   (GELEMS/4 = 32768)
    int c  = (gi >> 10) & (CH - 1);               // channel       (NSP/4 = 1024)
    float s = 0.f, sq = 0.f;
#pragma unroll
    for (int k = 0; k < 8; k++) {
        s  += g_gnpart[(bg*8 + k)*2 + 0];
        sq += g_gnpart[(bg*8 + k)*2 + 1];
    }
    float mean = s * (1.0f / GELEMS);
    float var  = sq * (1.0f / GELEMS) - mean * mean;
    float rstd = rsqrtf(var + EPS);
    float ga = gamma[c] * rstd;
    float be = beta[c] - mean * ga;
    float4 v = ((const float4*)x)[gi];
    float4 o;
    o.x = v.x*ga + be; o.y = v.y*ga + be; o.z = v.z*ga + be; o.w = v.w*ga + be;
    ((float4*)g_xn)[gi] = o;
}

// ---------------- Generic 64x64 tiled SGEMM ----------------
// C[b][m][n] = sum_k A[m][k] * B[...] + bias[m] (+ Res[b][m][n])
// BT=0: B is [K][N] per batch.  BT=1: B is [N][K] per batch.
template<int BT>
__global__ __launch_bounds__(256) void gemm64(
    const float* __restrict__ A, const float* __restrict__ Bg,
    const float* __restrict__ bias, const float* __restrict__ Res,
    float* __restrict__ Cg, int M, int N, int K,
    int strideB, int strideC, int strideR)
{
    __shared__ float As[16][68];
    __shared__ float Bs[16][68];
    int t = threadIdx.x;
    int tx = t & 15, ty = t >> 4;
    int n0 = blockIdx.x * 64, m0 = blockIdx.y * 64, b = blockIdx.z;
    const float* B = Bg + b * strideB;
    float* C = Cg + b * strideC;

    float acc[4][4] = {};
    int amm = t >> 2, ak4 = t & 3;      // A transpose-load mapping
    int bkk = t >> 4, bn4 = t & 15;     // BT=0 mapping
    int bnn = t >> 2, bk4 = t & 3;      // BT=1 mapping

    for (int k0 = 0; k0 < K; k0 += 16) {
        float4 av = *(const float4*)&A[(m0 + amm)*K + k0 + ak4*4];
        As[ak4*4+0][amm] = av.x; As[ak4*4+1][amm] = av.y;
        As[ak4*4+2][amm] = av.z; As[ak4*4+3][amm] = av.w;
        if (BT == 0) {
            float4 bv = *(const float4*)&B[(k0 + bkk)*N + n0 + bn4*4];
            *(float4*)&Bs[bkk][bn4*4] = bv;
        } else {
            float4 bv = *(const float4*)&B[(n0 + bnn)*K + k0 + bk4*4];
            Bs[bk4*4+0][bnn] = bv.x; Bs[bk4*4+1][bnn] = bv.y;
            Bs[bk4*4+2][bnn] = bv.z; Bs[bk4*4+3][bnn] = bv.w;
        }
        __syncthreads();
#pragma unroll
        for (int kk = 0; kk < 16; kk++) {
            float a[4], bv[4];
            *(float4*)a  = *(const float4*)&As[kk][ty*4];
            *(float4*)bv = *(const float4*)&Bs[kk][tx*4];
#pragma unroll
            for (int i = 0; i < 4; i++)
#pragma unroll
                for (int j = 0; j < 4; j++)
                    acc[i][j] += a[i] * bv[j];
        }
        __syncthreads();
    }

#pragma unroll
    for (int i = 0; i < 4; i++) {
        int m = m0 + ty*4 + i;
        float bi = bias[m];
        int off = m * N + n0 + tx*4;
        float4 o;
        o.x = acc[i][0] + bi; o.y = acc[i][1] + bi;
        o.z = acc[i][2] + bi; o.w = acc[i][3] + bi;
        if (Res) {
            float4 r = *(const float4*)&Res[b*strideR + off];
            o.x += r.x; o.y += r.y; o.z += r.z; o.w += r.w;
        }
        *(float4*)&C[off] = o;
    }
}

// ---------------- V transpose: [b][c][p] -> [b][p][c] ----------------
__global__ void transposeV(const float* __restrict__ qkv, float* __restrict__ vT) {
    __shared__ float tile[32][33];
    int b = blockIdx.z;
    int p0 = blockIdx.x * 32, c0 = blockIdx.y * 32;
    const float* V = qkv + (b*3*CH + 2*CH)*NSP;   // V section (channels 512..767)
    int tx = threadIdx.x, ty = threadIdx.y;       // 32 x 8
    for (int cc = ty; cc < 32; cc += 8)
        tile[cc][tx] = V[(c0 + cc)*NSP + p0 + tx];
    __syncthreads();
    for (int pp = ty; pp < 32; pp += 8)
        vT[(b*NSP + p0 + pp)*CH + c0 + tx] = tile[tx][pp];
}

// ---------------- Flash attention: BM=BN=64, c=256, online softmax ----------------
__global__ __launch_bounds__(256) void flash64(const float* __restrict__ qkv,
                                               const float* __restrict__ vT,
                                               float* __restrict__ out) {
    extern __shared__ float sm[];
    float* Qs  = sm;                 // [256][64]  (kc-major)
    float* Ks  = Qs + 256*64;        // [256][64]
    float* Vs  = Ks + 256*64;        // [64][260]  (j-major, padded)
    float* Ps  = Vs + 64*260;        // [64][68]
    float* mrow = Ps + 64*68;        // [64]
    float* lrow = mrow + 64;         // [64]
    float* arow = lrow + 64;         // [64]

    int t = threadIdx.x;
    int tx = t & 15, ty = t >> 4;
    int i0 = blockIdx.x * 64;
    int b  = blockIdx.y;
    const float* Qg = qkv + b*3*CH*NSP;          // channels 0..255
    const float* Kg = Qg + CH*NSP;               // channels 256..511
    const float* Vg = vT + b*NSP*CH;             // [p][c]

    // load Q tile (resident for entire CTA)
#pragma unroll
    for (int it = 0; it < 16; it++) {
        int task = it*256 + t;
        int kc = task >> 4, i4 = task & 15;
        float4 v = *(const float4*)&Qg[kc*NSP + i0 + i4*4];
        *(float4*)&Qs[kc*64 + i4*4] = v;
    }
    if (t < 64) { mrow[t] = -INFINITY; lrow[t] = 0.f; }

    float O[4][4][4];   // [ri][q][cc] -> channel = q*64 + tx*4 + cc
#pragma unroll
    for (int ri = 0; ri < 4; ri++)
#pragma unroll
        for (int q = 0; q < 4; q++)
#pragma unroll
            for (int cc = 0; cc < 4; cc++) O[ri][q][cc] = 0.f;
    __syncthreads();

    const float scale = 0.0625f;    // 1/sqrt(256)

    for (int j0 = 0; j0 < NSP; j0 += 64) {
        // load K tile [kc][j] and V tile [j][c]
#pragma unroll
        for (int it = 0; it < 16; it++) {
            int task = it*256 + t;
            int kc = task >> 4, j4 = task & 15;
            float4 v = *(const float4*)&Kg[kc*NSP + j0 + j4*4];
            *(float4*)&Ks[kc*64 + j4*4] = v;
        }
#pragma unroll
        for (int it = 0; it < 16; it++) {
            int task = it*256 + t;
            int j = task >> 6, c4 = task & 63;
            float4 v = *(const float4*)&Vg[(j0 + j)*CH + c4*4];
            *(float4*)&Vs[j*260 + c4*4] = v;
        }
        __syncthreads();

        // S = scale * Q^T K, 4x4 per thread
        float acc[4][4] = {};
#pragma unroll 8
        for (int kc = 0; kc < 256; kc++) {
            float a[4], bv[4];
            *(float4*)a  = *(const float4*)&Qs[kc*64 + ty*4];
            *(float4*)bv = *(const float4*)&Ks[kc*64 + tx*4];
#pragma unroll
            for (int i = 0; i < 4; i++)
#pragma unroll
                for (int j = 0; j < 4; j++)
                    acc[i][j] += a[i] * bv[j];
        }

        // online softmax update (row group = 16 lanes of one warp)
        float mnew[4], alv[4], rsum[4], mold[4];
#pragma unroll
        for (int ri = 0; ri < 4; ri++) {
#pragma unroll
            for (int cj = 0; cj < 4; cj++) acc[ri][cj] *= scale;
            float ml = fmaxf(fmaxf(acc[ri][0], acc[ri][1]),
                             fmaxf(acc[ri][2], acc[ri][3]));
            ml = fmaxf(ml, __shfl_xor_sync(0xffffffffu, ml, 8));
            ml = fmaxf(ml, __shfl_xor_sync(0xffffffffu, ml, 4));
            ml = fmaxf(ml, __shfl_xor_sync(0xffffffffu, ml, 2));
            ml = fmaxf(ml, __shfl_xor_sync(0xffffffffu, ml, 1));
            mold[ri] = mrow[ty*4 + ri];
            mnew[ri] = fmaxf(mold[ri], ml);
            float p[4]; float rs = 0.f;
#pragma unroll
            for (int cj = 0; cj < 4; cj++) {
                p[cj] = __expf(acc[ri][cj] - mnew[ri]);
                rs += p[cj];
            }
            rs += __shfl_xor_sync(0xffffffffu, rs, 8);
            rs += __shfl_xor_sync(0xffffffffu, rs, 4);
            rs += __shfl_xor_sync(0xffffffffu, rs, 2);
            rs += __shfl_xor_sync(0xffffffffu, rs, 1);
            rsum[ri] = rs;
            alv[ri]  = __expf(mold[ri] - mnew[ri]);
            *(float4*)&Ps[(ty*4 + ri)*68 + tx*4] = make_float4(p[0], p[1], p[2], p[3]);
        }
        __syncwarp();
        if (tx == 0) {
#pragma unroll
            for (int ri = 0; ri < 4; ri++) {
                int r = ty*4 + ri;
                mrow[r] = mnew[ri];
                lrow[r] = lrow[r]*alv[ri] + rsum[ri];
                arow[r] = alv[ri];
            }
        }
        __syncthreads();

        // rescale O, then O += P @ V
#pragma unroll
        for (int ri = 0; ri < 4; ri++) {
            float al = arow[ty*4 + ri];
#pragma unroll
            for (int q = 0; q < 4; q++)
#pragma unroll
                for (int cc = 0; cc < 4; cc++) O[ri][q][cc] *= al;
        }
#pragma unroll 2
        for (int j = 0; j < 64; j++) {
            float pr[4];
#pragma unroll
            for (int ri = 0; ri < 4; ri++) pr[ri] = Ps[(ty*4 + ri)*68 + j];
#pragma unroll
            for (int q = 0; q < 4; q++) {
                float vv[4];
                *(float4*)vv = *(const float4*)&Vs[j*260 + q*64 + tx*4];
#pragma unroll
                for (int ri = 0; ri < 4; ri++)
#pragma unroll
                    for (int cc = 0; cc < 4; cc++)
                        O[ri][q][cc] += pr[ri] * vv[cc];
            }
        }
        __syncthreads();
    }

    // normalize and write out[b][p][c]
#pragma unroll
    for (int ri = 0; ri < 4; ri++) {
        float inv = 1.0f / lrow[ty*4 + ri];
        int p = i0 + ty*4 + ri;
#pragma unroll
        for (int q = 0; q < 4; q++) {
            float4 o;
            o.x = O[ri][q][0]*inv; o.y = O[ri][q][1]*inv;
            o.z = O[ri][q][2]*inv; o.w = O[ri][q][3]*inv;
            *(float4*)&out[(b*NSP + p)*CH + q*64 + tx*4] = o;
        }
    }
}

// ---------------- launch ----------------
extern "C" void kernel_launch(void* const* d_in, const int* in_sizes, int n_in,
                              void* d_out, int out_size) {
    const float* x      = (const float*)d_in[0];
    const float* gamma  = (const float*)d_in[1];
    const float* beta   = (const float*)d_in[2];
    const float* w_qkv  = (const float*)d_in[3];
    const float* b_qkv  = (const float*)d_in[4];
    const float* w_proj = (const float*)d_in[5];
    const float* b_proj = (const float*)d_in[6];
    float* out = (float*)d_out;

    float *p_xn, *p_qkv, *p_vT, *p_attn;
    cudaGetSymbolAddress((void**)&p_xn,   g_xn);
    cudaGetSymbolAddress((void**)&p_qkv,  g_qkv);
    cudaGetSymbolAddress((void**)&p_vT,   g_vT);
    cudaGetSymbolAddress((void**)&p_attn, g_attn);

    // 1-2. GroupNorm
    gn_partial<<<BATCH*GROUPS*8, 256>>>(x);
    gn_apply<<<BATCH*CH*NSP/4/256, 256>>>(x, gamma, beta);

    // 3. QKV 1x1 conv: [768x256] x [256x4096] per batch
    gemm64<0><<<dim3(NSP/64, 3*CH/64, BATCH), 256>>>(
        w_qkv, p_xn, b_qkv, nullptr, p_qkv,
        3*CH, NSP, CH, CH*NSP, 3*CH*NSP, 0);

    // 4. V transpose -> [b][p][c]
    transposeV<<<dim3(NSP/32, CH/32, BATCH), dim3(32, 8)>>>(p_qkv, p_vT);

    // 5. flash attention -> g_attn [b][p][c]
    size_t smem = (size_t)(256*64*2 + 64*260 + 64*68 + 192) * sizeof(float);
    cudaFuncSetAttribute(flash64, cudaFuncAttributeMaxDynamicSharedMemorySize, (int)smem);
    flash64<<<dim3(NSP/64, BATCH), 256, smem>>>(p_qkv, p_vT, p_attn);

    // 6. proj + bias + residual -> out [b][c][h][w]
    gemm64<1><<<dim3(NSP/64, CH/64, BATCH), 256>>>(
        w_proj, p_attn, b_proj, x, out,
        CH, NSP, CH, NSP*CH, CH*NSP, CH*NSP);
}

// round 3
// speedup vs baseline: 1.0007x; 1.0007x over previous
#include <cuda_runtime.h>
#include <math.h>

#define BATCH 4
#define CH 256
#define NSP 4096            // h*w = 64*64
#define GROUPS 8
#define CPG 32              // channels per group
#define GELEMS (CPG*NSP)    // 131072 elements per (b, group)
#define EPS 1e-5f

// ---------------- scratch (device globals; no allocation allowed) ----------------
__device__ float g_xn[BATCH*CH*NSP];        // groupnorm output            16.8 MB
__device__ float g_qkv[BATCH*3*CH*NSP];     // qkv conv output [b][o][p]   50.3 MB
__device__ float g_vT[BATCH*NSP*CH];        // V transposed   [b][p][c]    16.8 MB
__device__ float g_attn[BATCH*NSP*CH];      // attn output    [b][p][c]    16.8 MB
__device__ float g_gnpart[BATCH*GROUPS*8*2];

// ---------------- GroupNorm: partial reduction ----------------
__global__ void gn_partial(const float* __restrict__ x) {
    int blk = blockIdx.x;          // 32 (b,g) * 8 slices
    int bg = blk >> 3, slice = blk & 7;
    const float4* p4 = (const float4*)(x + bg*GELEMS + slice*(GELEMS/8));
    float s = 0.f, sq = 0.f;
    for (int i = threadIdx.x; i < GELEMS/8/4; i += 256) {
        float4 v = p4[i];
        s  += v.x + v.y + v.z + v.w;
        sq += v.x*v.x + v.y*v.y + v.z*v.z + v.w*v.w;
    }
    __shared__ float ss[256], ssq[256];
    ss[threadIdx.x] = s; ssq[threadIdx.x] = sq;
    __syncthreads();
    for (int st = 128; st > 0; st >>= 1) {
        if (threadIdx.x < st) {
            ss[threadIdx.x]  += ss[threadIdx.x + st];
            ssq[threadIdx.x] += ssq[threadIdx.x + st];
        }
        __syncthreads();
    }
    if (threadIdx.x == 0) {
        g_gnpart[blk*2 + 0] = ss[0];
        g_gnpart[blk*2 + 1] = ssq[0];
    }
}

// ---------------- GroupNorm: apply ----------------
__global__ void gn_apply(const float* __restrict__ x,
                         const float* __restrict__ gamma,
                         const float* __restrict__ beta) {
    int gi = blockIdx.x * 256 + threadIdx.x;     // float4 index
    int bg = gi >> 15;                            // (b,g) index   (GELEMS/4 = 32768)
    int c  = (gi >> 10) & (CH - 1);               // channel       (NSP/4 = 1024)
    float s = 0.f, sq = 0.f;
#pragma unroll
    for (int k = 0; k < 8; k++) {
        s  += g_gnpart[(bg*8 + k)*2 + 0];
        sq += g_gnpart[(bg*8 + k)*2 + 1];
    }
    float mean = s * (1.0f / GELEMS);
    float var  = sq * (1.0f / GELEMS) - mean * mean;
    float rstd = rsqrtf(var + EPS);
    float ga = gamma[c] * rstd;
    float be = beta[c] - mean * ga;
    float4 v = ((const float4*)x)[gi];
    float4 o;
    o.x = v.x*ga + be; o.y = v.y*ga + be; o.z = v.z*ga + be; o.w = v.w*ga + be;
    ((float4*)g_xn)[gi] = o;
}

// ---------------- Generic 64x64 tiled SGEMM ----------------
// C[b][m][n] = sum_k A[m][k] * B[...] + bias[m] (+ Res[b][m][n])
// BT=0: B is [K][N] per batch.  BT=1: B is [N][K] per batch.
template<int BT>
__global__ __launch_bounds__(256) void gemm64(
    const float* __restrict__ A, const float* __restrict__ Bg,
    const float* __restrict__ bias, const float* __restrict__ Res,
    float* __restrict__ Cg, int M, int N, int K,
    int strideB, int strideC, int strideR)
{
    __shared__ float As[16][68];
    __shared__ float Bs[16][68];
    int t = threadIdx.x;
    int tx = t & 15, ty = t >> 4;
    int n0 = blockIdx.x * 64, m0 = blockIdx.y * 64, b = blockIdx.z;
    const float* B = Bg + b * strideB;
    float* C = Cg + b * strideC;

    float acc[4][4] = {};
    int amm = t >> 2, ak4 = t & 3;      // A transpose-load mapping
    int bkk = t >> 4, bn4 = t & 15;     // BT=0 mapping
    int bnn = t >> 2, bk4 = t & 3;      // BT=1 mapping

    for (int k0 = 0; k0 < K; k0 += 16) {
        float4 av = *(const float4*)&A[(m0 + amm)*K + k0 + ak4*4];
        As[ak4*4+0][amm] = av.x; As[ak4*4+1][amm] = av.y;
        As[ak4*4+2][amm] = av.z; As[ak4*4+3][amm] = av.w;
        if (BT == 0) {
            float4 bv = *(const float4*)&B[(k0 + bkk)*N + n0 + bn4*4];
            *(float4*)&Bs[bkk][bn4*4] = bv;
        } else {
            float4 bv = *(const float4*)&B[(n0 + bnn)*K + k0 + bk4*4];
            Bs[bk4*4+0][bnn] = bv.x; Bs[bk4*4+1][bnn] = bv.y;
            Bs[bk4*4+2][bnn] = bv.z; Bs[bk4*4+3][bnn] = bv.w;
        }
        __syncthreads();
#pragma unroll
        for (int kk = 0; kk < 16; kk++) {
            float a[4], bv[4];
            *(float4*)a  = *(const float4*)&As[kk][ty*4];
            *(float4*)bv = *(const float4*)&Bs[kk][tx*4];
#pragma unroll
            for (int i = 0; i < 4; i++)
#pragma unroll
                for (int j = 0; j < 4; j++)
                    acc[i][j] += a[i] * bv[j];
        }
        __syncthreads();
    }

#pragma unroll
    for (int i = 0; i < 4; i++) {
        int m = m0 + ty*4 + i;
        float bi = bias[m];
        int off = m * N + n0 + tx*4;
        float4 o;
        o.x = acc[i][0] + bi; o.y = acc[i][1] + bi;
        o.z = acc[i][2] + bi; o.w = acc[i][3] + bi;
        if (Res) {
            float4 r = *(const float4*)&Res[b*strideR + off];
            o.x += r.x; o.y += r.y; o.z += r.z; o.w += r.w;
        }
        *(float4*)&C[off] = o;
    }
}

// ---------------- V transpose: [b][c][p] -> [b][p][c] ----------------
__global__ void transposeV(const float* __restrict__ qkv, float* __restrict__ vT) {
    __shared__ float tile[32][33];
    int b = blockIdx.z;
    int p0 = blockIdx.x * 32, c0 = blockIdx.y * 32;
    const float* V = qkv + (b*3*CH + 2*CH)*NSP;   // V section (channels 512..767)
    int tx = threadIdx.x, ty = threadIdx.y;       // 32 x 8
    for (int cc = ty; cc < 32; cc += 8)
        tile[cc][tx] = V[(c0 + cc)*NSP + p0 + tx];
    __syncthreads();
    for (int pp = ty; pp < 32; pp += 8)
        vT[(b*NSP + p0 + pp)*CH + c0 + tx] = tile[tx][pp];
}

// ---------------- Flash attention: BM=BN=64, c=256, online softmax ----------------
__global__ __launch_bounds__(256) void flash64(const float* __restrict__ qkv,
                                               const float* __restrict__ vT,
                                               float* __restrict__ out) {
    extern __shared__ float sm[];
    float* Qs  = sm;                 // [256][64]  (kc-major)
    float* Ks  = Qs + 256*64;        // [256][64]
    float* Vs  = Ks + 256*64;        // [64][260]  (j-major, padded)
    float* Ps  = Vs + 64*260;        // [64][68]
    float* mrow = Ps + 64*68;        // [64]
    float* lrow = mrow + 64;         // [64]
    float* arow = lrow + 64;         // [64]

    int t = threadIdx.x;
    int tx = t & 15, ty = t >> 4;
    int i0 = blockIdx.x * 64;
    int b  = blockIdx.y;
    const float* Qg = qkv + b*3*CH*NSP;          // channels 0..255
    const float* Kg = Qg + CH*NSP;               // channels 256..511
    const float* Vg = vT + b*NSP*CH;             // [p][c]

    // load Q tile (resident for entire CTA)
#pragma unroll
    for (int it = 0; it < 16; it++) {
        int task = it*256 + t;
        int kc = task >> 4, i4 = task & 15;
        float4 v = *(const float4*)&Qg[kc*NSP + i0 + i4*4];
        *(float4*)&Qs[kc*64 + i4*4] = v;
    }
    if (t < 64) { mrow[t] = -INFINITY; lrow[t] = 0.f; }

    float O[4][4][4];   // [ri][q][cc] -> channel = q*64 + tx*4 + cc
#pragma unroll
    for (int ri = 0; ri < 4; ri++)
#pragma unroll
        for (int q = 0; q < 4; q++)
#pragma unroll
            for (int cc = 0; cc < 4; cc++) O[ri][q][cc] = 0.f;
    __syncthreads();

    const float scale = 0.0625f;    // 1/sqrt(256)

    for (int j0 = 0; j0 < NSP; j0 += 64) {
        // load K tile [kc][j] and V tile [j][c]
#pragma unroll
        for (int it = 0; it < 16; it++) {
            int task = it*256 + t;
            int kc = task >> 4, j4 = task & 15;
            float4 v = *(const float4*)&Kg[kc*NSP + j0 + j4*4];
            *(float4*)&Ks[kc*64 + j4*4] = v;
        }
#pragma unroll
        for (int it = 0; it < 16; it++) {
            int task = it*256 + t;
            int j = task >> 6, c4 = task & 63;
            float4 v = *(const float4*)&Vg[(j0 + j)*CH + c4*4];
            *(float4*)&Vs[j*260 + c4*4] = v;
        }
        __syncthreads();

        // S = scale * Q^T K, 4x4 per thread
        float acc[4][4] = {};
#pragma unroll 8
        for (int kc = 0; kc < 256; kc++) {
            float a[4], bv[4];
            *(float4*)a  = *(const float4*)&Qs[kc*64 + ty*4];
            *(float4*)bv = *(const float4*)&Ks[kc*64 + tx*4];
#pragma unroll
            for (int i = 0; i < 4; i++)
#pragma unroll
                for (int j = 0; j < 4; j++)
                    acc[i][j] += a[i] * bv[j];
        }

        // online softmax update (row group = 16 lanes of one warp)
        float mnew[4], alv[4], rsum[4], mold[4];
#pragma unroll
        for (int ri = 0; ri < 4; ri++) {
#pragma unroll
            for (int cj = 0; cj < 4; cj++) acc[ri][cj] *= scale;
            float ml = fmaxf(fmaxf(acc[ri][0], acc[ri][1]),
                             fmaxf(acc[ri][2], acc[ri][3]));
            ml = fmaxf(ml, __shfl_xor_sync(0xffffffffu, ml, 8));
            ml = fmaxf(ml, __shfl_xor_sync(0xffffffffu, ml, 4));
            ml = fmaxf(ml, __shfl_xor_sync(0xffffffffu, ml, 2));
            ml = fmaxf(ml, __shfl_xor_sync(0xffffffffu, ml, 1));
            mold[ri] = mrow[ty*4 + ri];
            mnew[ri] = fmaxf(mold[ri], ml);
            float p[4]; float rs = 0.f;
#pragma unroll
            for (int cj = 0; cj < 4; cj++) {
                p[cj] = __expf(acc[ri][cj] - mnew[ri]);
                rs += p[cj];
            }
            rs += __shfl_xor_sync(0xffffffffu, rs, 8);
            rs += __shfl_xor_sync(0xffffffffu, rs, 4);
            rs += __shfl_xor_sync(0xffffffffu, rs, 2);
            rs += __shfl_xor_sync(0xffffffffu, rs, 1);
            rsum[ri] = rs;
            alv[ri]  = __expf(mold[ri] - mnew[ri]);
            *(float4*)&Ps[(ty*4 + ri)*68 + tx*4] = make_float4(p[0], p[1], p[2], p[3]);
        }
        __syncwarp();
        if (tx == 0) {
#pragma unroll
            for (int ri = 0; ri < 4; ri++) {
                int r = ty*4 + ri;
                mrow[r] = mnew[ri];
                lrow[r] = lrow[r]*alv[ri] + rsum[ri];
                arow[r] = alv[ri];
            }
        }
        __syncthreads();

        // rescale O, then O += P @ V
#pragma unroll
        for (int ri = 0; ri < 4; ri++) {
            float al = arow[ty*4 + ri];
#pragma unroll
            for (int q = 0; q < 4; q++)
#pragma unroll
                for (int cc = 0; cc < 4; cc++) O[ri][q][cc] *= al;
        }
#pragma unroll 2
        for (int j = 0; j < 64; j++) {
            float pr[4];
#pragma unroll
            for (int ri = 0; ri < 4; ri++) pr[ri] = Ps[(ty*4 + ri)*68 + j];
#pragma unroll
            for (int q = 0; q < 4; q++) {
                float vv[4];
                *(float4*)vv = *(const float4*)&Vs[j*260 + q*64 + tx*4];
#pragma unroll
                for (int ri = 0; ri < 4; ri++)
#pragma unroll
                    for (int cc = 0; cc < 4; cc++)
                        O[ri][q][cc] += pr[ri] * vv[cc];
            }
        }
        __syncthreads();
    }

    // normalize and write out[b][p][c]
#pragma unroll
    for (int ri = 0; ri < 4; ri++) {
        float inv = 1.0f / lrow[ty*4 + ri];
        int p = i0 + ty*4 + ri;
#pragma unroll
        for (int q = 0; q < 4; q++) {
            float4 o;
            o.x = O[ri][q][0]*inv; o.y = O[ri][q][1]*inv;
            o.z = O[ri][q][2]*inv; o.w = O[ri][q][3]*inv;
            *(float4*)&out[(b*NSP + p)*CH + q*64 + tx*4] = o;
        }
    }
}

// ---------------- launch ----------------
extern "C" void kernel_launch(void* const* d_in, const int* in_sizes, int n_in,
                              void* d_out, int out_size) {
    const float* x      = (const float*)d_in[0];
    const float* gamma  = (const float*)d_in[1];
    const float* beta   = (const float*)d_in[2];
    const float* w_qkv  = (const float*)d_in[3];
    const float* b_qkv  = (const float*)d_in[4];
    const float* w_proj = (const float*)d_in[5];
    const float* b_proj = (const float*)d_in[6];
    float* out = (float*)d_out;

    float *p_xn, *p_qkv, *p_vT, *p_attn;
    cudaGetSymbolAddress((void**)&p_xn,   g_xn);
    cudaGetSymbolAddress((void**)&p_qkv,  g_qkv);
    cudaGetSymbolAddress((void**)&p_vT,   g_vT);
    cudaGetSymbolAddress((void**)&p_attn, g_attn);

    // 1-2. GroupNorm
    gn_partial<<<BATCH*GROUPS*8, 256>>>(x);
    gn_apply<<<BATCH*CH*NSP/4/256, 256>>>(x, gamma, beta);

    // 3. QKV 1x1 conv: [768x256] x [256x4096] per batch
    gemm64<0><<<dim3(NSP/64, 3*CH/64, BATCH), 256>>>(
        w_qkv, p_xn, b_qkv, nullptr, p_qkv,
        3*CH, NSP, CH, CH*NSP, 3*CH*NSP, 0);

    // 4. V transpose -> [b][p][c]
    transposeV<<<dim3(NSP/32, CH/32, BATCH), dim3(32, 8)>>>(p_qkv, p_vT);

    // 5. flash attention -> g_attn [b][p][c]
    size_t smem = (size_t)(256*64*2 + 64*260 + 64*68 + 192) * sizeof(float);
    cudaFuncSetAttribute(flash64, cudaFuncAttributeMaxDynamicSharedMemorySize, (int)smem);
    flash64<<<dim3(NSP/64, BATCH), 256, smem>>>(p_qkv, p_vT, p_attn);

    // 6. proj + bias + residual -> out [b][c][h][w]
    gemm64<1><<<dim3(NSP/64, CH/64, BATCH), 256>>>(
        w_proj, p_attn, b_proj, x, out,
        CH, NSP, CH, NSP*CH, CH*NSP, CH*NSP);
}

// round 9
// speedup vs baseline: 3.3287x; 3.3263x over previous
#include <cuda_runtime.h>
#include <math.h>
#include <stdint.h>

#define BATCH 4
#define CH 256
#define NSP 4096            // h*w
#define GROUPS 8
#define GELEMS (32*NSP)     // elems per (b,group)
#define EPS 1e-5f

// ---------------- scratch (device globals) ----------------
__device__ float g_xnt [BATCH*NSP*CH];      // groupnorm output, token-major [b][p][c]
__device__ float g_qkvt[BATCH*NSP*3*CH];    // qkv, token-major [b][p][768]
__device__ float g_vt  [BATCH*CH*NSP];      // V [b][c][p]
__device__ float g_S   [(size_t)BATCH*NSP*NSP]; // scores / P   268 MB
__device__ float g_linv[BATCH*NSP];         // 1/rowsum
__device__ float g_attn[BATCH*NSP*CH];      // attention out [b][p][c]
__device__ float g_gnpart[BATCH*GROUPS*8*2];

// ---------------- GroupNorm partial reduction ----------------
__global__ void gn_partial(const float* __restrict__ x) {
    int blk = blockIdx.x;
    int bg = blk >> 3, slice = blk & 7;
    const float4* p4 = (const float4*)(x + bg*GELEMS + slice*(GELEMS/8));
    float s = 0.f, sq = 0.f;
    for (int i = threadIdx.x; i < GELEMS/8/4; i += 256) {
        float4 v = p4[i];
        s  += v.x + v.y + v.z + v.w;
        sq += v.x*v.x + v.y*v.y + v.z*v.z + v.w*v.w;
    }
    __shared__ float ss[256], ssq[256];
    ss[threadIdx.x] = s; ssq[threadIdx.x] = sq;
    __syncthreads();
    for (int st = 128; st > 0; st >>= 1) {
        if (threadIdx.x < st) {
            ss[threadIdx.x]  += ss[threadIdx.x + st];
            ssq[threadIdx.x] += ssq[threadIdx.x + st];
        }
        __syncthreads();
    }
    if (threadIdx.x == 0) {
        g_gnpart[blk*2 + 0] = ss[0];
        g_gnpart[blk*2 + 1] = ssq[0];
    }
}

// ---------------- GroupNorm apply + transpose -> [b][p][c] ----------------
__global__ void gn_apply_t(const float* __restrict__ x,
                           const float* __restrict__ gamma,
                           const float* __restrict__ beta) {
    __shared__ float tile[32][33];
    __shared__ float s_ga[32], s_be[32];
    int b = blockIdx.z;
    int p0 = blockIdx.x*32, c0 = blockIdx.y*32;
    int tx = threadIdx.x, ty = threadIdx.y;   // 32 x 8
    if (ty == 0) {
        int c = c0 + tx;
        int bg = b*GROUPS + (c >> 5);
        float s = 0.f, sq = 0.f;
#pragma unroll
        for (int k = 0; k < 8; k++) { s += g_gnpart[(bg*8+k)*2]; sq += g_gnpart[(bg*8+k)*2+1]; }
        float mean = s * (1.f/GELEMS);
        float var  = sq * (1.f/GELEMS) - mean*mean;
        float rstd = rsqrtf(var + EPS);
        float ga = gamma[c]*rstd;
        s_ga[tx] = ga; s_be[tx] = beta[c] - mean*ga;
    }
    __syncthreads();
    const float* X = x + (size_t)b*CH*NSP;
    for (int cc = ty; cc < 32; cc += 8)
        tile[cc][tx] = X[(c0+cc)*NSP + p0+tx]*s_ga[cc] + s_be[cc];
    __syncthreads();
    float* O = g_xnt + (size_t)b*NSP*CH;
    for (int pp = ty; pp < 32; pp += 8)
        O[(p0+pp)*CH + c0+tx] = tile[tx][pp];
}

// ---------------- V transpose: qkvt [p][768] cols 512..767 -> g_vt [c][p] ----------------
__global__ void transposeVt() {
    __shared__ float tile[32][33];
    int b = blockIdx.z;
    int p0 = blockIdx.x*32, c0 = blockIdx.y*32;
    int tx = threadIdx.x, ty = threadIdx.y;
    const float* Q = g_qkvt + (size_t)b*NSP*768;
    for (int pp = ty; pp < 32; pp += 8)
        tile[pp][tx] = Q[(size_t)(p0+pp)*768 + 512 + c0 + tx];
    __syncthreads();
    float* V = g_vt + (size_t)b*CH*NSP;
    for (int cc = ty; cc < 32; cc += 8)
        V[(c0+cc)*NSP + p0 + tx] = tile[tx][cc];
}

// ---------------- fast exp on FMA pipe (avoid MUFU bottleneck) ----------------
__device__ __forceinline__ float fast_exp(float x) {
    x = fmaxf(x, -87.0f);
    float y = x * 1.44269504f;
    float t = y + 12582912.0f;            // round-to-nearest via magic number
    int   n = __float_as_int(t) - 0x4B400000;
    float f = y - (t - 12582912.0f);      // f in [-0.5, 0.5]
    float p = 0.00133335581f;
    p = fmaf(p, f, 0.00961812911f);
    p = fmaf(p, f, 0.0555041087f);
    p = fmaf(p, f, 0.240226507f);
    p = fmaf(p, f, 0.693147181f);
    p = fmaf(p, f, 1.0f);
    return __int_as_float(__float_as_int(p) + (n << 23));
}

// ---------------- rowwise softmax (unnormalized; stores 1/sum) ----------------
__global__ __launch_bounds__(128) void softmax_rows() {
    size_t row = blockIdx.x;
    float* S = g_S + row * NSP;
    int t = threadIdx.x;
    float4 v[8];
    float mx = -1e30f;
#pragma unroll
    for (int i = 0; i < 8; i++) {
        v[i] = ((float4*)S)[t + i*128];
        mx = fmaxf(mx, fmaxf(fmaxf(v[i].x, v[i].y), fmaxf(v[i].z, v[i].w)));
    }
#pragma unroll
    for (int o = 16; o > 0; o >>= 1) mx = fmaxf(mx, __shfl_xor_sync(~0u, mx, o));
    __shared__ float sm[4];
    if ((t & 31) == 0) sm[t >> 5] = mx;
    __syncthreads();
    mx = fmaxf(fmaxf(sm[0], sm[1]), fmaxf(sm[2], sm[3]));
    const float scale = 0.0625f;   // 1/sqrt(256)
    float sum = 0.f;
#pragma unroll
    for (int i = 0; i < 8; i++) {
        v[i].x = fast_exp((v[i].x - mx)*scale);
        v[i].y = fast_exp((v[i].y - mx)*scale);
        v[i].z = fast_exp((v[i].z - mx)*scale);
        v[i].w = fast_exp((v[i].w - mx)*scale);
        sum += v[i].x + v[i].y + v[i].z + v[i].w;
        ((float4*)S)[t + i*128] = v[i];
    }
#pragma unroll
    for (int o = 16; o > 0; o >>= 1) sum += __shfl_xor_sync(~0u, sum, o);
    __syncthreads();
    if ((t & 31) == 0) sm[t >> 5] = sum;
    __syncthreads();
    if (t == 0) g_linv[row] = 1.0f / (sm[0] + sm[1] + sm[2] + sm[3]);
}

// ---------------- tf32 mma.sync GEMM: D[M,N] = A[M,K] x B[N,K]^T ----------------
// BM=128, BN=128, BK=32. 8 warps (2x4), warp tile 64x32, mma m16n8k8.
// SMEM tiles K-major, row stride 36 floats => fragment loads hit all 32 banks.
// EPI: 0 = +bias[n]   (qkv)
//      1 = none       (scores)
//      2 = *aux[m]    (PV, 1/l)
//      3 = +bias[m] + res[m][n] (proj)
#define BM 128
#define BN 128
#define BK 32
#define TSTRIDE 36
#define TILEF (128*TSTRIDE)               // floats per tile
#define SMEMSZ (4*TILEF*4)                // A0,A1,B0,B1

#define MMA_TF32(d, a, b) \
    asm volatile("mma.sync.aligned.m16n8k8.row.col.f32.tf32.tf32.f32 " \
        "{%0,%1,%2,%3}, {%4,%5,%6,%7}, {%8,%9}, {%0,%1,%2,%3};" \
        : "+f"((d)[0]), "+f"((d)[1]), "+f"((d)[2]), "+f"((d)[3]) \
        : "r"((a)[0]), "r"((a)[1]), "r"((a)[2]), "r"((a)[3]), \
          "r"((b)[0]), "r"((b)[1]))

template<int EPI>
__global__ __launch_bounds__(256) void mm_tf32(
    const float* __restrict__ Ag, int lda, long sAb,
    const float* __restrict__ Bg, int ldb, long sBb,
    float* __restrict__ Cg, int ldc, long sCb,
    const float* __restrict__ bias,
    const float* __restrict__ auxg, long sXb,
    int K)
{
    extern __shared__ float smf[];
    float* As[2] = { smf,           smf + TILEF };
    float* Bs[2] = { smf + 2*TILEF, smf + 3*TILEF };

    int t = threadIdx.x;
    int wid = t >> 5, lane = t & 31;
    int g = lane >> 2, tg = lane & 3;
    int wm = wid >> 2, wn = wid & 3;          // 2 x 4 warp grid
    int n0 = blockIdx.x * BN, m0 = blockIdx.y * BM;
    long b = blockIdx.z;
    const float* A = Ag + b*sAb;
    const float* B = Bg + b*sBb;
    float* C = Cg + b*sCb;

    // cp.async tile loaders: 128 rows x 32 floats, 8 threads per row (16B each)
    int lrow = t >> 3, lc = (t & 7) * 4;
    auto loadA = [&](int buf, int k0) {
        uint32_t sbase = (uint32_t)__cvta_generic_to_shared(As[buf]);
#pragma unroll
        for (int i = 0; i < 4; i++) {
            int row = lrow + i*32;
            uint32_t so = sbase + (row*TSTRIDE + lc) * 4;
            const float* gp = A + (long)(m0+row)*lda + k0 + lc;
            asm volatile("cp.async.cg.shared.global [%0], [%1], 16;" :: "r"(so), "l"(gp));
        }
    };
    auto loadB = [&](int buf, int k0) {
        uint32_t sbase = (uint32_t)__cvta_generic_to_shared(Bs[buf]);
#pragma unroll
        for (int i = 0; i < 4; i++) {
            int row = lrow + i*32;
            uint32_t so = sbase + (row*TSTRIDE + lc) * 4;
            const float* gp = B + (long)(n0+row)*ldb + k0 + lc;
            asm volatile("cp.async.cg.shared.global [%0], [%1], 16;" :: "r"(so), "l"(gp));
        }
    };

    float acc[4][4][4];
#pragma unroll
    for (int mi = 0; mi < 4; mi++)
#pragma unroll
        for (int nj = 0; nj < 4; nj++)
#pragma unroll
            for (int r = 0; r < 4; r++) acc[mi][nj][r] = 0.f;

    const int NK = K / BK;
    loadA(0, 0); loadB(0, 0);
    asm volatile("cp.async.commit_group;" ::: "memory");

    int cur = 0;
    for (int kt = 0; kt < NK; kt++) {
        if (kt + 1 < NK) {
            loadA(cur ^ 1, (kt+1)*BK);
            loadB(cur ^ 1, (kt+1)*BK);
            asm volatile("cp.async.commit_group;" ::: "memory");
            asm volatile("cp.async.wait_group 1;" ::: "memory");
        } else {
            asm volatile("cp.async.wait_group 0;" ::: "memory");
        }
        __syncthreads();

        const uint32_t* Aw = (const uint32_t*)(As[cur] + (wm*64 + g)*TSTRIDE + tg);
        const uint32_t* Bw = (const uint32_t*)(Bs[cur] + (wn*32 + g)*TSTRIDE + tg);
#pragma unroll
        for (int kk = 0; kk < BK; kk += 8) {
            uint32_t af[4][4], bf[4][2];
#pragma unroll
            for (int mi = 0; mi < 4; mi++) {
                const uint32_t* p = Aw + mi*16*TSTRIDE + kk;
                af[mi][0] = p[0];
                af[mi][1] = p[8*TSTRIDE];
                af[mi][2] = p[4];
                af[mi][3] = p[8*TSTRIDE + 4];
            }
#pragma unroll
            for (int nj = 0; nj < 4; nj++) {
                const uint32_t* p = Bw + nj*8*TSTRIDE + kk;
                bf[nj][0] = p[0];
                bf[nj][1] = p[4];
            }
#pragma unroll
            for (int mi = 0; mi < 4; mi++)
#pragma unroll
                for (int nj = 0; nj < 4; nj++)
                    MMA_TF32(acc[mi][nj], af[mi], bf[nj]);
        }
        __syncthreads();
        cur ^= 1;
    }

    // ---- epilogue: acc layout d0:(g, 2tg) d1:(g, 2tg+1) d2:(g+8, 2tg) d3:(g+8, 2tg+1)
    int mb = m0 + wm*64;
    int nb = n0 + wn*32;
#pragma unroll
    for (int mi = 0; mi < 4; mi++) {
        int r0 = mb + mi*16 + g;
        int r1 = r0 + 8;
        float mul0 = 1.f, mul1 = 1.f, add0 = 0.f, add1 = 0.f;
        if (EPI == 2) { mul0 = auxg[b*sXb + r0]; mul1 = auxg[b*sXb + r1]; }
        if (EPI == 3) { add0 = bias[r0];         add1 = bias[r1]; }
#pragma unroll
        for (int nj = 0; nj < 4; nj++) {
            int col = nb + nj*8 + tg*2;
            float2 v0 = make_float2(acc[mi][nj][0], acc[mi][nj][1]);
            float2 v1 = make_float2(acc[mi][nj][2], acc[mi][nj][3]);
            if (EPI == 0) {
                float2 bv = *(const float2*)&bias[col];
                v0.x += bv.x; v0.y += bv.y; v1.x += bv.x; v1.y += bv.y;
            }
            v0.x = v0.x*mul0 + add0; v0.y = v0.y*mul0 + add0;
            v1.x = v1.x*mul1 + add1; v1.y = v1.y*mul1 + add1;
            long o0 = (long)r0*ldc + col;
            long o1 = (long)r1*ldc + col;
            if (EPI == 3) {
                const float* R = auxg + b*sXb;
                float2 x0 = *(const float2*)&R[o0];
                float2 x1 = *(const float2*)&R[o1];
                v0.x += x0.x; v0.y += x0.y; v1.x += x1.x; v1.y += x1.y;
            }
            *(float2*)&C[o0] = v0;
            *(float2*)&C[o1] = v1;
        }
    }
}

// ---------------- launch ----------------
extern "C" void kernel_launch(void* const* d_in, const int* in_sizes, int n_in,
                              void* d_out, int out_size) {
    const float* x      = (const float*)d_in[0];
    const float* gamma  = (const float*)d_in[1];
    const float* beta   = (const float*)d_in[2];
    const float* w_qkv  = (const float*)d_in[3];
    const float* b_qkv  = (const float*)d_in[4];
    const float* w_proj = (const float*)d_in[5];
    const float* b_proj = (const float*)d_in[6];
    float* out = (float*)d_out;

    float *p_xnt, *p_qkvt, *p_vt, *p_S, *p_linv, *p_attn;
    cudaGetSymbolAddress((void**)&p_xnt,  g_xnt);
    cudaGetSymbolAddress((void**)&p_qkvt, g_qkvt);
    cudaGetSymbolAddress((void**)&p_vt,   g_vt);
    cudaGetSymbolAddress((void**)&p_S,    g_S);
    cudaGetSymbolAddress((void**)&p_linv, g_linv);
    cudaGetSymbolAddress((void**)&p_attn, g_attn);

    cudaFuncSetAttribute(mm_tf32<0>, cudaFuncAttributeMaxDynamicSharedMemorySize, SMEMSZ);
    cudaFuncSetAttribute(mm_tf32<1>, cudaFuncAttributeMaxDynamicSharedMemorySize, SMEMSZ);
    cudaFuncSetAttribute(mm_tf32<2>, cudaFuncAttributeMaxDynamicSharedMemorySize, SMEMSZ);
    cudaFuncSetAttribute(mm_tf32<3>, cudaFuncAttributeMaxDynamicSharedMemorySize, SMEMSZ);

    // 1-2. GroupNorm (apply fused with transpose to token-major)
    gn_partial<<<BATCH*GROUPS*8, 256>>>(x);
    gn_apply_t<<<dim3(NSP/32, CH/32, BATCH), dim3(32, 8)>>>(x, gamma, beta);

    // 3. QKV: D[p][o] = xnt[p][c] * w_qkv[o][c]^T + b_qkv[o]
    mm_tf32<0><<<dim3(3*CH/BN, NSP/BM, BATCH), 256, SMEMSZ>>>(
        p_xnt, CH, (long)NSP*CH,
        w_qkv, CH, 0,
        p_qkvt, 3*CH, (long)NSP*3*CH,
        b_qkv, nullptr, 0, CH);

    // 4. V -> [c][p]
    transposeVt<<<dim3(NSP/32, CH/32, BATCH), dim3(32, 8)>>>();

    // 5. S[i][j] = Q[i][c] * K[j][c]^T   (raw logits; scale folded into softmax)
    mm_tf32<1><<<dim3(NSP/BN, NSP/BM, BATCH), 256, SMEMSZ>>>(
        p_qkvt,       3*CH, (long)NSP*3*CH,
        p_qkvt + CH,  3*CH, (long)NSP*3*CH,
        p_S, NSP, (long)NSP*NSP,
        nullptr, nullptr, 0, CH);

    // 6. softmax rows (unnormalized P, stores 1/l)
    softmax_rows<<<BATCH*NSP, 128>>>();

    // 7. O[i][c] = P[i][j] * Vt[c][j]^T, scaled by 1/l[i]
    mm_tf32<2><<<dim3(CH/BN, NSP/BM, BATCH), 256, SMEMSZ>>>(
        p_S, NSP, (long)NSP*NSP,
        p_vt, NSP, (long)CH*NSP,
        p_attn, CH, (long)NSP*CH,
        nullptr, p_linv, NSP, NSP);

    // 8. out[co][p] = w_proj[co][c] * attn[p][c]^T + b_proj[co] + x
    mm_tf32<3><<<dim3(NSP/BN, CH/BM, BATCH), 256, SMEMSZ>>>(
        w_proj, CH, 0,
        p_attn, CH, (long)NSP*CH,
        out, NSP, (long)CH*NSP,
        b_proj, x, (long)CH*NSP, CH);
}